// round 16
// baseline (speedup 1.0000x reference)
#include <cuda_runtime.h>
#include <cuda_bf16.h>
#include <math.h>

// ChainCRF: B=128, S=256, C=64.
// TWO WARPS per batch row (128 CTAs x 64 threads). Thread j owns column j.
// Linear-domain forward recursion; power-of-two renorm every 4 steps folded
// into that step's emission multiplier; log taken once at the end.
// Per step: 16 broadcast LDS.128, 32 fma.rn.f32x2 in four chains, STS.32,
// one __syncthreads. NO smem staging beyond the q double buffer: expU column
// and all path-energy operands are loaded to registers in the prologue, so
// their memory latency hides under the 255-step main loop.

#define Bc 128
#define Sc 256
#define Cc 64
#define Tc 64

__device__ float g_batch_res[Bc];
__device__ unsigned int g_ticket = 0;

#define FMA2(d,a,b,c)  asm("fma.rn.f32x2 %0, %1, %2, %3;" : "=l"(d) : "l"(a), "l"(b), "l"(c))
#define ADD2(d,a,b)    asm("add.rn.f32x2 %0, %1, %2;" : "=l"(d) : "l"(a), "l"(b))
#define PACK2(d,lo,hi) asm("mov.b64 %0, {%1, %2};" : "=l"(d) : "f"(lo), "f"(hi))
#define UNPACK2(lo,hi,s) asm("mov.b64 {%0, %1}, %2;" : "=f"(lo), "=f"(hi) : "l"(s))

// Core step: q_new[j] = (sum_i q_i * expU[i][j]) * EMXV.  4 accumulator chains.
#define STEP_CORE(QR, QW, EMXV) do {                                           \
    unsigned long long _a0 = 0ull, _a1 = 0ull, _a2 = 0ull, _a3 = 0ull;         \
    const ulonglong2* _qv = (const ulonglong2*)(QR);                           \
    _Pragma("unroll")                                                          \
    for (int _c = 0; _c < 8; ++_c) {                                           \
        ulonglong2 _v = _qv[2 * _c];                                           \
        ulonglong2 _w = _qv[2 * _c + 1];                                       \
        FMA2(_a0, _v.x, rE[4*_c+0], _a0);                                      \
        FMA2(_a1, _v.y, rE[4*_c+1], _a1);                                      \
        FMA2(_a2, _w.x, rE[4*_c+2], _a2);                                      \
        FMA2(_a3, _w.y, rE[4*_c+3], _a3);                                      \
    }                                                                          \
    ADD2(_a0, _a0, _a1);                                                       \
    ADD2(_a2, _a2, _a3);                                                       \
    ADD2(_a0, _a0, _a2);                                                       \
    float _lo, _hi;                                                            \
    UNPACK2(_lo, _hi, _a0);                                                    \
    (QW)[j] = (_lo + _hi) * (EMXV);                                            \
    __syncthreads();                                                           \
} while (0)

// Renormalizing step: exponent of q[0], exact 2^-k folded into EMX.
#define STEP_R(QR, QW, EX) do {                                                \
    float _q0 = (QR)[0];                                                       \
    int   _k  = (int)((__float_as_uint(_q0) >> 23) & 0xFF) - 127;              \
    K += _k;                                                                   \
    float _emx = (EX) * __uint_as_float((unsigned)(127 - _k) << 23);           \
    STEP_CORE(QR, QW, _emx);                                                   \
} while (0)

#define STEP_N(QR, QW, EX) STEP_CORE(QR, QW, (EX))

__global__ __launch_bounds__(Tc, 1)
void crf_kernel(const float* __restrict__ em,
                const int*   __restrict__ tags,
                const float* __restrict__ mask,
                const float* __restrict__ U,
                float* __restrict__ out)
{
    const int b = blockIdx.x;
    const int j = threadIdx.x;           // column owned by this thread (0..63)
    const int l = j & 31;                // lane
    const int w = j >> 5;                // warp (0,1)

    __shared__ __align__(16) float qA[Cc];
    __shared__ __align__(16) float qB[Cc];
    __shared__ float red[2];

    const float* emb   = em   + (size_t)b * Sc * Cc;
    const float* mb    = mask + (size_t)b * Sc;
    const int*   tagsb = tags + (size_t)b * Sc;

    // ---- expU column straight from global U (coalesced across threads) ----
    float uu[Cc];
#pragma unroll
    for (int i = 0; i < Cc; ++i) uu[i] = U[i * Cc + j];   // 64 LDG.32, MLP 64

    // ---- path-energy operands to REGISTERS (independent of the recursion;
    //      latency hides under the main loop) ----
    int   tga[4]; float mba[4];          // tags/mask at t = j + 64k
    int   tgn[4]; float mbn[4];          // tags/mask at t = 1 + j + 64k
#pragma unroll
    for (int k = 0; k < 4; ++k) {
        int t = j + 64 * k;
        tga[k] = tagsb[t];
        mba[k] = mb[t];
    }
#pragma unroll
    for (int k = 0; k < 4; ++k) {
        int t = 1 + j + 64 * k;
        if (t < Sc) { tgn[k] = tagsb[t]; mbn[k] = mb[t]; }
        else        { tgn[k] = 0;        mbn[k] = 0.0f;  }
    }
    // dependent gathers (em-tag term, U-transition term)
    float eg[4], utr[4];
#pragma unroll
    for (int k = 0; k < 4; ++k) {
        int tm = (int)((float)tga[k] * mba[k]);
        eg[k]  = emb[(j + 64 * k) * Cc + tm];
        utr[k] = U[tga[k] * Cc + tgn[k]];
    }

    // q(0) = exp(em[0])
    qA[j] = __expf(emb[j]);

    // pack exp(U) column into 32 u64 (MUFU burst; overlaps the loads above)
    unsigned long long rE[32];
#pragma unroll
    for (int p = 0; p < 32; ++p) {
        float e0 = __expf(uu[2 * p + 0]);
        float e1 = __expf(uu[2 * p + 1]);
        PACK2(rE[p], e0, e1);            // {E[2p][j], E[2p+1][j]}
    }

    // mask uniformity from the registers already loaded
    int ok = 1;
#pragma unroll
    for (int k = 0; k < 4; ++k) {
        ok &= (mba[k] == 1.0f);
        int t = 1 + j + 64 * k;
        if (t < Sc) ok &= (mbn[k] == 1.0f);
    }

    int K = 0;
    // single prologue barrier: orders the q seed, reduces ok
    ok = __syncthreads_and(ok);

    if (ok) {
        // ---- fast path: 4-step chunks, renorm once per chunk ----
        float c0 = emb[1 * Cc + j], c1 = emb[2 * Cc + j], c2 = emb[3 * Cc + j];
        float ex0 = __expf(c0), ex1 = __expf(c1), ex2 = __expf(c2);
        float d0 = emb[4 * Cc + j], d1 = emb[5 * Cc + j];
        float d2 = emb[6 * Cc + j], d3 = emb[7 * Cc + j];

        STEP_R(qA, qB, ex0);             // t = 1  (renorm)
        STEP_N(qB, qA, ex1);             // t = 2
        STEP_N(qA, qB, ex2);             // t = 3

        // main chunks t = 4..248: prefetch t+4..t+7 <= 255, guard-free
#pragma unroll 1
        for (int t = 4; t < 252; t += 4) {
            float e0 = __expf(d0), e1 = __expf(d1);
            float e2 = __expf(d2), e3 = __expf(d3);
            float n0 = emb[(t + 4) * Cc + j];
            float n1 = emb[(t + 5) * Cc + j];
            float n2 = emb[(t + 6) * Cc + j];
            float n3 = emb[(t + 7) * Cc + j];

            STEP_R(qB, qA, e0);          // t     (renorm)
            STEP_N(qA, qB, e1);          // t + 1
            STEP_N(qB, qA, e2);          // t + 2
            STEP_N(qA, qB, e3);          // t + 3

            d0 = n0; d1 = n1; d2 = n2; d3 = n3;
        }
        // peeled final chunk t = 252..255 (no prefetch)
        {
            float e0 = __expf(d0), e1 = __expf(d1);
            float e2 = __expf(d2), e3 = __expf(d3);
            STEP_R(qB, qA, e0);          // 252 (renorm)
            STEP_N(qA, qB, e1);          // 253
            STEP_N(qB, qA, e2);          // 254
            STEP_N(qA, qB, e3);          // 255 -> q in qB
        }
    } else {
        // ---- generic masked fallback (never taken in this dataset) ----
        const float* qr = qA; float* qw = qB;
        for (int t = 1; t < Sc; ++t) {
            float m   = mb[t];
            float emv = emb[t * Cc + j];
            float q0  = qr[0];
            int   k   = (int)((__float_as_uint(q0) >> 23) & 0xFF) - 127;
            float sc  = __uint_as_float((unsigned)(127 - k) << 23);
            K += k;

            float s;
            if (m == 1.0f) {
                float a = 0.f;
                for (int i = 0; i < Cc; ++i)
                    a = fmaf(qr[i], __expf(U[i * Cc + j]), a);
                s = a * __expf(emv);
            } else if (m == 0.0f) {
                float a = 0.f;
                for (int i = 0; i < Cc; ++i) a += qr[i];
                s = a;
            } else {
                float a = 0.f;
                for (int i = 0; i < Cc; ++i)
                    a += qr[i] * __expf((emv + U[i * Cc + j]) * m);
                s = a;
            }
            qw[j] = s * sc;
            __syncthreads();
            const float* tr = qr; qr = qw; qw = const_cast<float*>(tr);
        }
        // t=255 (odd) wrote qB
    }

    // ---- path energy from prologue registers (no memory on the chain) ----
    float pe = 0.0f;
#pragma unroll
    for (int k = 0; k < 4; ++k) {
        pe = fmaf(eg[k],  mba[k], pe);   // emission-tag term
        pe = fmaf(utr[k], mbn[k], pe);   // transition term (mbn=0 when t>=Sc)
    }
#pragma unroll
    for (int o = 16; o > 0; o >>= 1)
        pe += __shfl_xor_sync(0xFFFFFFFFu, pe, o);
    if (l == 0) red[w] = pe;
    __syncthreads();

    // ---- free energy + per-batch result + fused finalize ----
    if (j == 0) {
        float qs = 0.0f;
#pragma unroll
        for (int i = 0; i < Cc; ++i) qs += qB[i];
        float fe = logf(qs) + (float)K * 0.6931471805599453f;
        g_batch_res[b] = fe - (red[0] + red[1]);
        __threadfence();
    }
    __syncthreads();

    if (w == 0) {
        unsigned int old = 0;
        if (l == 0) old = atomicAdd(&g_ticket, 1u);
        old = __shfl_sync(0xFFFFFFFFu, old, 0);
        if (old == Bc - 1) {
            __threadfence();
            float v = 0.0f;
#pragma unroll
            for (int i = 0; i < Bc / 32; ++i) v += g_batch_res[l + 32 * i];
#pragma unroll
            for (int o = 16; o > 0; o >>= 1)
                v += __shfl_xor_sync(0xFFFFFFFFu, v, o);
            if (l == 0) {
                out[0] = v * (1.0f / (float)Bc);
                g_ticket = 0;              // reset for next graph replay
            }
        }
    }
}

extern "C" void kernel_launch(void* const* d_in, const int* in_sizes, int n_in,
                              void* d_out, int out_size)
{
    const float* emissions = (const float*)d_in[0];
    const int*   true_tags = (const int*)  d_in[1];
    const float* mask      = (const float*)d_in[2];
    const float* U         = (const float*)d_in[3];
    float* out = (float*)d_out;

    crf_kernel<<<Bc, Tc>>>(emissions, true_tags, mask, U, out);
}

// round 17
// speedup vs baseline: 1.0126x; 1.0126x over previous
#include <cuda_runtime.h>
#include <cuda_bf16.h>
#include <math.h>

// ChainCRF: B=128, S=256, C=64.
// TWO WARPS per batch row (128 CTAs x 64 threads). Thread j owns column j.
// Linear-domain forward recursion; power-of-two renorm every 4 steps folded
// into that step's emission multiplier; log taken once at the end.
// Per step: 16 broadcast LDS.128, 32 fma.rn.f32x2 in four chains, STS.32,
// one __syncthreads. Prologue: rE from global U concurrent with smem staging
// (R14); path-energy operands INCLUDING dependent gathers prefetched to
// registers so the epilogue has no memory on the critical path (R16).

#define Bc 128
#define Sc 256
#define Cc 64
#define Tc 64

__device__ float g_batch_res[Bc];
__device__ unsigned int g_ticket = 0;

#define FMA2(d,a,b,c)  asm("fma.rn.f32x2 %0, %1, %2, %3;" : "=l"(d) : "l"(a), "l"(b), "l"(c))
#define ADD2(d,a,b)    asm("add.rn.f32x2 %0, %1, %2;" : "=l"(d) : "l"(a), "l"(b))
#define PACK2(d,lo,hi) asm("mov.b64 %0, {%1, %2};" : "=l"(d) : "f"(lo), "f"(hi))
#define UNPACK2(lo,hi,s) asm("mov.b64 {%0, %1}, %2;" : "=f"(lo), "=f"(hi) : "l"(s))

// Core step: q_new[j] = (sum_i q_i * expU[i][j]) * EMXV.  4 accumulator chains.
#define STEP_CORE(QR, QW, EMXV) do {                                           \
    unsigned long long _a0 = 0ull, _a1 = 0ull, _a2 = 0ull, _a3 = 0ull;         \
    const ulonglong2* _qv = (const ulonglong2*)(QR);                           \
    _Pragma("unroll")                                                          \
    for (int _c = 0; _c < 8; ++_c) {                                           \
        ulonglong2 _v = _qv[2 * _c];                                           \
        ulonglong2 _w = _qv[2 * _c + 1];                                       \
        FMA2(_a0, _v.x, rE[4*_c+0], _a0);                                      \
        FMA2(_a1, _v.y, rE[4*_c+1], _a1);                                      \
        FMA2(_a2, _w.x, rE[4*_c+2], _a2);                                      \
        FMA2(_a3, _w.y, rE[4*_c+3], _a3);                                      \
    }                                                                          \
    ADD2(_a0, _a0, _a1);                                                       \
    ADD2(_a2, _a2, _a3);                                                       \
    ADD2(_a0, _a0, _a2);                                                       \
    float _lo, _hi;                                                            \
    UNPACK2(_lo, _hi, _a0);                                                    \
    (QW)[j] = (_lo + _hi) * (EMXV);                                            \
    __syncthreads();                                                           \
} while (0)

// Renormalizing step: exponent of q[0], exact 2^-k folded into EMX.
#define STEP_R(QR, QW, EX) do {                                                \
    float _q0 = (QR)[0];                                                       \
    int   _k  = (int)((__float_as_uint(_q0) >> 23) & 0xFF) - 127;              \
    K += _k;                                                                   \
    float _emx = (EX) * __uint_as_float((unsigned)(127 - _k) << 23);           \
    STEP_CORE(QR, QW, _emx);                                                   \
} while (0)

#define STEP_N(QR, QW, EX) STEP_CORE(QR, QW, (EX))

__global__ __launch_bounds__(Tc, 1)
void crf_kernel(const float* __restrict__ em,
                const int*   __restrict__ tags,
                const float* __restrict__ mask,
                const float* __restrict__ U,
                float* __restrict__ out)
{
    const int b = blockIdx.x;
    const int j = threadIdx.x;           // column owned by this thread (0..63)
    const int l = j & 31;                // lane
    const int w = j >> 5;                // warp (0,1)

    __shared__ __align__(16) float qA[Cc];
    __shared__ __align__(16) float qB[Cc];
    __shared__ __align__(16) float sU[Cc * Cc];
    __shared__ float red[2];

    const float* emb   = em   + (size_t)b * Sc * Cc;
    const float* mb    = mask + (size_t)b * Sc;
    const int*   tagsb = tags + (size_t)b * Sc;

    // ---- rE straight from global U (coalesced per i across threads);
    //      issued first so DRAM latency overlaps everything below ----
    float uu[Cc];
#pragma unroll
    for (int i = 0; i < Cc; ++i) uu[i] = U[i * Cc + j];   // 64 LDG.32, MLP 64

    // ---- path-energy operands to registers (independent of recursion) ----
    int   tga[4]; float mba[4];          // tags/mask at t = j + 64k
    int   tgn[4]; float mbn[4];          // tags/mask at t = 1 + j + 64k
#pragma unroll
    for (int k = 0; k < 4; ++k) {
        int t = j + 64 * k;
        tga[k] = tagsb[t];
        mba[k] = mb[t];
    }
#pragma unroll
    for (int k = 0; k < 4; ++k) {
        int t = 1 + j + 64 * k;
        if (t < Sc) { tgn[k] = tagsb[t]; mbn[k] = mb[t]; }
        else        { tgn[k] = 0;        mbn[k] = 0.0f;  }
    }
    // dependent gathers (em-tag, U-transition) — latency hides under the loop
    float eg[4], utr[4];
#pragma unroll
    for (int k = 0; k < 4; ++k) {
        int tm = (int)((float)tga[k] * mba[k]);
        eg[k]  = emb[(j + 64 * k) * Cc + tm];
        utr[k] = U[tga[k] * Cc + tgn[k]];
    }

    // ---- stage sU for the fallback path (overlaps the loads above) ----
    {
        const float4* U4  = (const float4*)U;
        float4*       sU4 = (float4*)sU;
#pragma unroll
        for (int i = 0; i < (Cc * Cc / 4) / Tc; ++i)     // 16 iters
            sU4[j + Tc * i] = U4[j + Tc * i];
    }
    qA[j] = __expf(emb[j]);              // q(0) = exp(em[0])

    // pack exp(U) column into 32 u64 (MUFU burst; overlaps staging)
    unsigned long long rE[32];
#pragma unroll
    for (int p = 0; p < 32; ++p) {
        float e0 = __expf(uu[2 * p + 0]);
        float e1 = __expf(uu[2 * p + 1]);
        PACK2(rE[p], e0, e1);            // {E[2p][j], E[2p+1][j]}
    }

    // mask uniformity from the registers already loaded
    int ok = 1;
#pragma unroll
    for (int k = 0; k < 4; ++k) {
        ok &= (mba[k] == 1.0f);
        int t = 1 + j + 64 * k;
        if (t < Sc) ok &= (mbn[k] == 1.0f);
    }

    int K = 0;
    // single prologue barrier: orders staging + q seed, reduces ok
    ok = __syncthreads_and(ok);

    if (ok) {
        // ---- fast path: 4-step chunks, renorm once per chunk ----
        float c0 = emb[1 * Cc + j], c1 = emb[2 * Cc + j], c2 = emb[3 * Cc + j];
        float ex0 = __expf(c0), ex1 = __expf(c1), ex2 = __expf(c2);
        float d0 = emb[4 * Cc + j], d1 = emb[5 * Cc + j];
        float d2 = emb[6 * Cc + j], d3 = emb[7 * Cc + j];

        STEP_R(qA, qB, ex0);             // t = 1  (renorm)
        STEP_N(qB, qA, ex1);             // t = 2
        STEP_N(qA, qB, ex2);             // t = 3

        // main chunks t = 4..248: prefetch t+4..t+7 <= 255, guard-free
#pragma unroll 1
        for (int t = 4; t < 252; t += 4) {
            float e0 = __expf(d0), e1 = __expf(d1);
            float e2 = __expf(d2), e3 = __expf(d3);
            float n0 = emb[(t + 4) * Cc + j];
            float n1 = emb[(t + 5) * Cc + j];
            float n2 = emb[(t + 6) * Cc + j];
            float n3 = emb[(t + 7) * Cc + j];

            STEP_R(qB, qA, e0);          // t     (renorm)
            STEP_N(qA, qB, e1);          // t + 1
            STEP_N(qB, qA, e2);          // t + 2
            STEP_N(qA, qB, e3);          // t + 3

            d0 = n0; d1 = n1; d2 = n2; d3 = n3;
        }
        // peeled final chunk t = 252..255 (no prefetch)
        {
            float e0 = __expf(d0), e1 = __expf(d1);
            float e2 = __expf(d2), e3 = __expf(d3);
            STEP_R(qB, qA, e0);          // 252 (renorm)
            STEP_N(qA, qB, e1);          // 253
            STEP_N(qB, qA, e2);          // 254
            STEP_N(qA, qB, e3);          // 255 -> q in qB
        }
    } else {
        // ---- generic masked fallback (never taken in this dataset) ----
        const float* qr = qA; float* qw = qB;
        for (int t = 1; t < Sc; ++t) {
            float m   = mb[t];
            float emv = emb[t * Cc + j];
            float q0  = qr[0];
            int   k   = (int)((__float_as_uint(q0) >> 23) & 0xFF) - 127;
            float sc  = __uint_as_float((unsigned)(127 - k) << 23);
            K += k;

            float s;
            if (m == 1.0f) {
                float a = 0.f;
                for (int i = 0; i < Cc; ++i)
                    a = fmaf(qr[i], __expf(sU[i * Cc + j]), a);
                s = a * __expf(emv);
            } else if (m == 0.0f) {
                float a = 0.f;
                for (int i = 0; i < Cc; ++i) a += qr[i];
                s = a;
            } else {
                float a = 0.f;
                for (int i = 0; i < Cc; ++i)
                    a += qr[i] * __expf((emv + sU[i * Cc + j]) * m);
                s = a;
            }
            qw[j] = s * sc;
            __syncthreads();
            const float* tr = qr; qr = qw; qw = const_cast<float*>(tr);
        }
        // t=255 (odd) wrote qB
    }

    // ---- path energy from prologue registers (no memory on the chain) ----
    float pe = 0.0f;
#pragma unroll
    for (int k = 0; k < 4; ++k) {
        pe = fmaf(eg[k],  mba[k], pe);   // emission-tag term
        pe = fmaf(utr[k], mbn[k], pe);   // transition term (mbn=0 when t>=Sc)
    }
#pragma unroll
    for (int o = 16; o > 0; o >>= 1)
        pe += __shfl_xor_sync(0xFFFFFFFFu, pe, o);
    if (l == 0) red[w] = pe;
    __syncthreads();

    // ---- free energy + per-batch result + fused finalize ----
    if (j == 0) {
        float qs = 0.0f;
#pragma unroll
        for (int i = 0; i < Cc; ++i) qs += qB[i];
        float fe = logf(qs) + (float)K * 0.6931471805599453f;
        g_batch_res[b] = fe - (red[0] + red[1]);
        __threadfence();
    }
    __syncthreads();

    if (w == 0) {
        unsigned int old = 0;
        if (l == 0) old = atomicAdd(&g_ticket, 1u);
        old = __shfl_sync(0xFFFFFFFFu, old, 0);
        if (old == Bc - 1) {
            __threadfence();
            float v = 0.0f;
#pragma unroll
            for (int i = 0; i < Bc / 32; ++i) v += g_batch_res[l + 32 * i];
#pragma unroll
            for (int o = 16; o > 0; o >>= 1)
                v += __shfl_xor_sync(0xFFFFFFFFu, v, o);
            if (l == 0) {
                out[0] = v * (1.0f / (float)Bc);
                g_ticket = 0;              // reset for next graph replay
            }
        }
    }
}

extern "C" void kernel_launch(void* const* d_in, const int* in_sizes, int n_in,
                              void* d_out, int out_size)
{
    const float* emissions = (const float*)d_in[0];
    const int*   true_tags = (const int*)  d_in[1];
    const float* mask      = (const float*)d_in[2];
    const float* U         = (const float*)d_in[3];
    float* out = (float*)d_out;

    crf_kernel<<<Bc, Tc>>>(emissions, true_tags, mask, U, out);
}